// round 17
// baseline (speedup 1.0000x reference)
#include <cuda_runtime.h>
#include <cuda_fp16.h>
#include <cstdint>

// ---------------- problem constants ----------------
constexpr int Bq = 4096;
constexpr int Eq = 512;   // K
constexpr int Tq = 32;
constexpr int Hq = 256;
constexpr int ITq = 5;
#define EPSq 1e-6f

constexpr int EPIT = 514;                    // epilogue pitch (floats)
constexpr int SMEM_BYTES = 32 * EPIT * 4;    // 65792 B per CTA

// ---------------- fragment-ready scratch ----------------
// A frags: [mtile32 128][ks 32][mfrag 2][lane 32][8 halves]       = 4 MB
// B frags: [tok 32][ks 32][warp 8][fpair 4][lane 32][8 halves]    = 16 MB
__device__ __align__(256) __half g_xa[(size_t)128 * 32 * 2 * 32 * 8];
__device__ __align__(256) __half g_xb[(size_t)32 * 32 * 8 * 4 * 32 * 8];

__device__ __forceinline__ void mma16816(float* d, const uint32_t* a,
                                         const uint32_t* b) {
    asm volatile(
        "mma.sync.aligned.m16n8k16.row.col.f32.f16.f16.f32 "
        "{%0,%1,%2,%3},{%4,%5,%6,%7},{%8,%9},{%0,%1,%2,%3};"
        : "+f"(d[0]), "+f"(d[1]), "+f"(d[2]), "+f"(d[3])
        : "r"(a[0]), "r"(a[1]), "r"(a[2]), "r"(a[3]), "r"(b[0]), "r"(b[1]));
}

// non-coherent 16-byte load (read-only, L1-cached — used for A, which is reused)
__device__ __forceinline__ uint4 ldg_nc16(const uint4* p) {
    uint4 v;
    asm volatile("ld.global.nc.v4.u32 {%0,%1,%2,%3}, [%4];"
                 : "=r"(v.x), "=r"(v.y), "=r"(v.z), "=r"(v.w) : "l"(p));
    return v;
}
// streaming 16-byte load: bypass L1 allocation (B — zero reuse)
__device__ __forceinline__ uint4 ldg_stream16(const uint4* p) {
    uint4 v;
    asm volatile("ld.global.nc.L1::no_allocate.v4.u32 {%0,%1,%2,%3}, [%4];"
                 : "=r"(v.x), "=r"(v.y), "=r"(v.z), "=r"(v.w) : "l"(p));
    return v;
}

// ---------------- kernel 1: fused conversions ----------------
// blocks [0,1024):     x -> A fragments (float2 loads)
// blocks [1024,5120):  w -> B fragments (64x32 tile per block)
__global__ __launch_bounds__(256)
void convert_kernel(const float* __restrict__ x,
                    const float* __restrict__ w_in,
                    const float* __restrict__ w_val) {
    __shared__ float tile[64][33];
    if (blockIdx.x < 1024) {
        const int idx   = blockIdx.x * 256 + threadIdx.x;
        const int lane  = idx & 31;
        const int mfrag = (idx >> 5) & 1;
        const int ks    = (idx >> 6) & 31;
        const int mtile = idx >> 11;
        const int r0 = mtile * 32 + mfrag * 16 + (lane >> 2);
        const int c0 = ks * 16 + 2 * (lane & 3);
        const float2* p0 = reinterpret_cast<const float2*>(x + (size_t)r0 * Eq + c0);
        const float2* p1 = reinterpret_cast<const float2*>(x + (size_t)(r0 + 8) * Eq + c0);
        float2 v00 = p0[0], v01 = p0[4];
        float2 v10 = p1[0], v11 = p1[4];
        __half h[8];
        h[0] = __float2half_rn(v00.x); h[1] = __float2half_rn(v00.y);
        h[2] = __float2half_rn(v10.x); h[3] = __float2half_rn(v10.y);
        h[4] = __float2half_rn(v01.x); h[5] = __float2half_rn(v01.y);
        h[6] = __float2half_rn(v11.x); h[7] = __float2half_rn(v11.y);
        reinterpret_cast<uint4*>(g_xa)[idx] = *reinterpret_cast<uint4*>(h);
        return;
    }
    const int bz = blockIdx.x - 1024;       // 0..4095
    const int e0 = (bz & 7) * 64;
    const int h0 = ((bz >> 3) & 7) * 32;
    const int z  = bz >> 6;
    const int m  = z >> 5;
    const int t  = z & 31;
    const float* src = (m ? w_val : w_in) + (size_t)t * Eq * Hq;
    const int tx = threadIdx.x & 31;
    const int ty = threadIdx.x >> 5;
    #pragma unroll
    for (int r = ty; r < 64; r += 8)
        tile[r][tx] = src[(size_t)(e0 + r) * Hq + h0 + tx];
    __syncthreads();
    const int lane = threadIdx.x & 31;
    const int f    = (threadIdx.x >> 5) & 3;
    const int ksl  = threadIdx.x >> 7;
    const int hc   = f * 8 + (lane >> 2);
    const int wp   = h0 >> 5;
    const int fi   = f + m * 4;
    #pragma unroll
    for (int eh = 0; eh < 2; eh++) {
        const int ks = (e0 >> 4) + eh * 2 + ksl;
        const int k0 = eh * 32 + ksl * 16 + 2 * (lane & 3);
        __half hv[4];
        hv[0] = __float2half_rn(tile[k0][hc]);
        hv[1] = __float2half_rn(tile[k0 + 1][hc]);
        hv[2] = __float2half_rn(tile[k0 + 8][hc]);
        hv[3] = __float2half_rn(tile[k0 + 9][hc]);
        const size_t di = (((((size_t)t * 32 + ks) * 8 + wp) * 4 + (fi >> 1)) * 32
                          + lane) * 2 + (fi & 1);
        reinterpret_cast<uint2*>(g_xb)[di] = *reinterpret_cast<uint2*>(hv);
    }
}

// ---------------- kernel 2: all-LDG GEMM + single-barrier epilogue --------
__global__ __launch_bounds__(256, 2)
void gemm_fused_kernel(const float* __restrict__ alphas,
                       const float* __restrict__ scales,
                       const float* __restrict__ gamma,
                       const float* __restrict__ beta,
                       float* __restrict__ out)
{
    extern __shared__ float es[];   // [32 rows][EPIT]

    const int tid  = threadIdx.x;
    const int wid  = tid >> 5;
    const int lane = tid & 31;
    const int mtile = blockIdx.x;   // 0..127
    const int tok   = blockIdx.y;   // 0..31
    const int b0    = mtile * 32;

    const uint4* pa = reinterpret_cast<const uint4*>(g_xa)
                    + ((size_t)mtile * 32) * 2 * 32 + lane;
    const uint4* pb = reinterpret_cast<const uint4*>(g_xb)
                    + (((size_t)tok * 32) * 8 + wid) * 4 * 32 + lane;

    float acc[2][8][4];
    #pragma unroll
    for (int i = 0; i < 2; i++)
        #pragma unroll
        for (int j = 0; j < 8; j++)
            #pragma unroll
            for (int k = 0; k < 4; k++) acc[i][j][k] = 0.0f;

    uint4 a0[2], a1[2];
    uint4 bb0[4], bb1[4];

    #define LOAD_A(ks, A) do {                                   \
        A[0] = ldg_nc16(pa + (size_t)(ks) * 64);                 \
        A[1] = ldg_nc16(pa + (size_t)(ks) * 64 + 32);            \
    } while (0)
    #define LOAD_B(ks, BB) do {                                  \
        _Pragma("unroll")                                        \
        for (int j = 0; j < 4; j++)                              \
            BB[j] = ldg_stream16(pb + (size_t)(ks) * 1024 + j * 32); \
    } while (0)
    #define DO_MMA(A, BB) do {                                   \
        _Pragma("unroll")                                        \
        for (int mf = 0; mf < 2; mf++)                           \
            _Pragma("unroll")                                    \
            for (int f = 0; f < 8; f++)                          \
                mma16816(acc[mf][f],                             \
                         reinterpret_cast<const uint32_t*>(&A[mf]), \
                         reinterpret_cast<const uint32_t*>(&BB[f >> 1]) + (f & 1) * 2); \
    } while (0)

    LOAD_A(0, a0); LOAD_B(0, bb0);
    #pragma unroll
    for (int ks = 0; ks < 32; ks += 2) {
        if (ks + 1 < 32) { LOAD_A(ks + 1, a1); LOAD_B(ks + 1, bb1); }
        DO_MMA(a0, bb0);
        if (ks + 2 < 32) { LOAD_A(ks + 2, a0); LOAD_B(ks + 2, bb0); }
        if (ks + 1 < 32) DO_MMA(a1, bb1);
    }

    // ---------------- epilogue: one smem transpose, then warp-local rows ----
    #pragma unroll
    for (int mf = 0; mf < 2; mf++)
        #pragma unroll
        for (int f = 0; f < 8; f++) {
            const int row = mf * 16 + (lane >> 2);
            const int col = wid * 32 + ((f & 3) * 8) + 2 * (lane & 3)
                          + (f >> 2) * 256;
            *reinterpret_cast<float2*>(&es[row * EPIT + col]) =
                make_float2(acc[mf][f][0], acc[mf][f][1]);
            *reinterpret_cast<float2*>(&es[(row + 8) * EPIT + col]) =
                make_float2(acc[mf][f][2], acc[mf][f][3]);
        }
    __syncthreads();

    float av[ITq];
    #pragma unroll
    for (int i = 0; i < ITq; i++) av[i] = alphas[tok * ITq + i];

    float sc[8], gm[8], bt[8];
    #pragma unroll
    for (int j = 0; j < 8; j++) {
        sc[j] = scales[tok * Hq + 32 * j + lane];
        gm[j] = gamma [tok * Hq + 32 * j + lane];
        bt[j] = beta  [tok * Hq + 32 * j + lane];
    }

    constexpr float INVH = 1.0f / (float)Hq;
    #pragma unroll
    for (int rr = 0; rr < 4; rr++) {
        const int lrow = wid * 4 + rr;
        float xt[8], xv[8];
        #pragma unroll
        for (int j = 0; j < 8; j++) {
            xt[j] = fmaxf(es[lrow * EPIT + 32 * j + lane], 0.0f);
            xv[j] = es[lrow * EPIT + 256 + 32 * j + lane];
        }
        #pragma unroll
        for (int it = 0; it < ITq; it++) {
            float s = 0.0f;
            #pragma unroll
            for (int j = 0; j < 8; j++) s += xt[j];
            #pragma unroll
            for (int off = 16; off > 0; off >>= 1)
                s += __shfl_xor_sync(0xffffffffu, s, off);
            const float d = av[it] * s * INVH;
            #pragma unroll
            for (int j = 0; j < 8; j++) xt[j] = fmaxf(xt[j] - d, 0.0f);
        }
        float sv[8], sum = 0.0f, sq = 0.0f;
        #pragma unroll
        for (int j = 0; j < 8; j++) {
            sv[j] = sc[j] * xt[j] * xv[j];
            sum += sv[j];
            sq  += sv[j] * sv[j];
        }
        #pragma unroll
        for (int off = 16; off > 0; off >>= 1) {
            sum += __shfl_xor_sync(0xffffffffu, sum, off);
            sq  += __shfl_xor_sync(0xffffffffu, sq,  off);
        }
        const float mu  = sum * INVH;
        const float var = fmaxf(sq * INVH - mu * mu, 0.0f);
        const float inv = rsqrtf(var + EPSq);
        float* op = out + ((size_t)(b0 + lrow) * Tq + tok) * Hq;
        #pragma unroll
        for (int j = 0; j < 8; j++)
            op[32 * j + lane] = (sv[j] - mu) * inv * gm[j] + bt[j];
    }
}

// ---------------- host launch ----------------
extern "C" void kernel_launch(void* const* d_in, const int* in_sizes, int n_in,
                              void* d_out, int out_size) {
    const float* x      = (const float*)d_in[0];
    const float* w_in   = (const float*)d_in[1];
    const float* w_val  = (const float*)d_in[2];
    const float* alphas = (const float*)d_in[3];
    const float* scales = (const float*)d_in[4];
    const float* gamma  = (const float*)d_in[5];
    const float* beta   = (const float*)d_in[6];
    float* out = (float*)d_out;

    convert_kernel<<<1024 + 4096, 256>>>(x, w_in, w_val);

    cudaFuncSetAttribute(gemm_fused_kernel,
                         cudaFuncAttributeMaxDynamicSharedMemorySize, SMEM_BYTES);
    dim3 grid(Bq / 32, Tq);
    gemm_fused_kernel<<<grid, 256, SMEM_BYTES>>>(alphas, scales, gamma, beta, out);
}